// round 1
// baseline (speedup 1.0000x reference)
#include <cuda_runtime.h>

// CenterDirectionLoss — GB300 sm_103a
// Pipeline (5 launches, all graph-capturable, allocation-free):
//   k_zero  : zero the persistent __device__ histogram
//   k_hist  : per-batch 128-bin histogram of `instances` (smem int atomics)
//   k_norm  : global num_instances / num_bg scalars -> inv_norm[b][id]
//   k_main  : weighted |pred-gt| L1 reduction, per-block deterministic partials
//   k_out   : fixed-order combine of partials -> 5x16 outputs

#define NUM_IDS 128
#define BATCH   16
#define BLOCKS_PER_BATCH 74
#define THREADS 256

__device__ int   g_counts[BATCH * NUM_IDS];
__device__ float g_inv[BATCH * NUM_IDS];
__device__ float g_part_sin[BATCH * BLOCKS_PER_BATCH];
__device__ float g_part_cos[BATCH * BLOCKS_PER_BATCH];

__global__ void k_zero() {
    int i = blockIdx.x * blockDim.x + threadIdx.x;
    if (i < BATCH * NUM_IDS) g_counts[i] = 0;
}

// grid: (BLOCKS_PER_BATCH, BATCH), THREADS threads
__global__ void k_hist(const int* __restrict__ inst, int HW) {
    __shared__ int sh[NUM_IDS];
    const int b = blockIdx.y;
    for (int i = threadIdx.x; i < NUM_IDS; i += blockDim.x) sh[i] = 0;
    __syncthreads();

    const int4* __restrict__ p = (const int4*)(inst + (size_t)b * HW);
    const int n4 = HW >> 2;
    for (int i = blockIdx.x * blockDim.x + threadIdx.x; i < n4;
         i += gridDim.x * blockDim.x) {
        int4 v = p[i];
        atomicAdd(&sh[v.x], 1);
        atomicAdd(&sh[v.y], 1);
        atomicAdd(&sh[v.z], 1);
        atomicAdd(&sh[v.w], 1);
    }
    __syncthreads();
    for (int i = threadIdx.x; i < NUM_IDS; i += blockDim.x) {
        int c = sh[i];
        if (c) atomicAdd(&g_counts[b * NUM_IDS + i], c);
    }
}

// one block, 256 threads
__global__ void k_norm() {
    __shared__ float s_ni[256];
    __shared__ float s_bg[256];
    const int tid = threadIdx.x;

    float ni = 0.f, bg = 0.f;
    for (int i = tid; i < BATCH * NUM_IDS; i += 256) {
        int c  = g_counts[i];
        int id = i & (NUM_IDS - 1);
        if (id == 0) bg += (float)c;
        else         ni += (c > 0) ? 1.f : 0.f;
    }
    s_ni[tid] = ni; s_bg[tid] = bg;
    __syncthreads();
    for (int s = 128; s > 0; s >>= 1) {
        if (tid < s) { s_ni[tid] += s_ni[tid + s]; s_bg[tid] += s_bg[tid + s]; }
        __syncthreads();
    }
    const float num_inst = s_ni[0];
    const float num_bg   = s_bg[0];

    for (int i = tid; i < BATCH * NUM_IDS; i += 256) {
        int id   = i & (NUM_IDS - 1);
        float c  = (float)g_counts[i];
        float norm = (id == 0) ? (num_bg * 2.0f)
                               : (fmaxf(c, 1.0f) * num_inst * 2.0f);
        g_inv[i] = 1.0f / norm;
    }
}

// grid: (BLOCKS_PER_BATCH, BATCH), THREADS threads
__global__ void k_main(const float* __restrict__ pred,
                       const int*   __restrict__ inst,
                       const float* __restrict__ gt,
                       int HW) {
    __shared__ float s_inv[NUM_IDS];
    const int b = blockIdx.y;
    for (int i = threadIdx.x; i < NUM_IDS; i += blockDim.x)
        s_inv[i] = g_inv[b * NUM_IDS + i];
    __syncthreads();

    const size_t HWs = (size_t)HW;
    const float4* __restrict__ ps = (const float4*)(pred + (size_t)b * 2 * HWs);
    const float4* __restrict__ pc = (const float4*)(pred + (size_t)b * 2 * HWs + HWs);
    const float4* __restrict__ gs = (const float4*)(gt + (size_t)b * 5 * HWs + 2 * HWs);
    const float4* __restrict__ gc = (const float4*)(gt + (size_t)b * 5 * HWs + 3 * HWs);
    const int4*   __restrict__ pi = (const int4*)(inst + (size_t)b * HWs);

    float as = 0.f, ac = 0.f;
    const int n4 = HW >> 2;
    for (int i = blockIdx.x * blockDim.x + threadIdx.x; i < n4;
         i += gridDim.x * blockDim.x) {
        int4   id = pi[i];
        float4 a  = ps[i];
        float4 bq = pc[i];
        float4 c  = gs[i];
        float4 d  = gc[i];
        float w0 = s_inv[id.x], w1 = s_inv[id.y], w2 = s_inv[id.z], w3 = s_inv[id.w];
        as += w0 * fabsf(a.x - c.x) + w1 * fabsf(a.y - c.y)
            + w2 * fabsf(a.z - c.z) + w3 * fabsf(a.w - c.w);
        ac += w0 * fabsf(bq.x - d.x) + w1 * fabsf(bq.y - d.y)
            + w2 * fabsf(bq.z - d.z) + w3 * fabsf(bq.w - d.w);
    }

    // deterministic block reduction: warp shuffle -> smem -> thread 0
    #pragma unroll
    for (int o = 16; o > 0; o >>= 1) {
        as += __shfl_down_sync(0xFFFFFFFFu, as, o);
        ac += __shfl_down_sync(0xFFFFFFFFu, ac, o);
    }
    __shared__ float rs[THREADS / 32];
    __shared__ float rc[THREADS / 32];
    const int w = threadIdx.x >> 5, l = threadIdx.x & 31;
    if (l == 0) { rs[w] = as; rc[w] = ac; }
    __syncthreads();
    if (threadIdx.x == 0) {
        float ts = 0.f, tc = 0.f;
        #pragma unroll
        for (int i = 0; i < THREADS / 32; i++) { ts += rs[i]; tc += rc[i]; }
        g_part_sin[b * BLOCKS_PER_BATCH + blockIdx.x] = ts;
        g_part_cos[b * BLOCKS_PER_BATCH + blockIdx.x] = tc;
    }
}

// one block, 32 threads: fixed-order final sums + output layout
__global__ void k_out(float* __restrict__ out) {
    const int b = threadIdx.x;
    if (b < BATCH) {
        float s = 0.f, c = 0.f;
        #pragma unroll 4
        for (int i = 0; i < BLOCKS_PER_BATCH; i++) {
            s += g_part_sin[b * BLOCKS_PER_BATCH + i];
            c += g_part_cos[b * BLOCKS_PER_BATCH + i];
        }
        const float tot = s + c;
        out[0 * BATCH + b] = tot;   // loss
        out[1 * BATCH + b] = tot;   // loss_direction_total
        out[2 * BATCH + b] = 0.0f;  // loss_centers
        out[3 * BATCH + b] = s;     // loss_sin
        out[4 * BATCH + b] = c;     // loss_cos
    }
}

extern "C" void kernel_launch(void* const* d_in, const int* in_sizes, int n_in,
                              void* d_out, int out_size) {
    const float* pred = (const float*)d_in[0];   // (16, 2, 768, 768) f32
    const int*   inst = (const int*)d_in[1];     // (16, 768, 768) i32
    // d_in[2] = labels (unused: W_FG == W_BG == 1.0 and labels == instances>0)
    const float* gt   = (const float*)d_in[3];   // (16, 5, 768, 768) f32
    float*       out  = (float*)d_out;           // 5 x 16 f32

    const int HW = in_sizes[1] / BATCH;

    dim3 grid(BLOCKS_PER_BATCH, BATCH);
    k_zero<<<(BATCH * NUM_IDS + 255) / 256, 256>>>();
    k_hist<<<grid, THREADS>>>(inst, HW);
    k_norm<<<1, 256>>>();
    k_main<<<grid, THREADS>>>(pred, inst, gt, HW);
    k_out<<<1, 32>>>(out);
}